// round 1
// baseline (speedup 1.0000x reference)
#include <cuda_runtime.h>

#define B_ 8
#define N_ 1024
#define C_ 768
#define H_ 12
#define D_ 64
#define QKV3 (3 * C_)

// Scratch (static device arrays — allocation-free per harness rules)
__device__ float g_qkv[(size_t)B_ * N_ * QKV3];   // 75.5 MB: [B*N, 3C] = [.., t*768 + h*64 + d]
__device__ float g_att[(size_t)B_ * N_ * C_];     // 25.2 MB: attention output [B*N, C]

// ---------------------------------------------------------------------------
// Generic fp32 GEMM body: C[M,N] = A[M,K] @ B[K,N] + bias[N]
// 128x128x16 tile, 256 threads, 8x8 per-thread microtile (strided ownership).
// Assumes M%128==0, N%128==0, K%16==0 (true for all three call sites).
// ---------------------------------------------------------------------------
__device__ __forceinline__ void gemm_body(
    const float* __restrict__ A, const float* __restrict__ Bm,
    const float* __restrict__ bias, float* __restrict__ C,
    int M, int N, int K)
{
    __shared__ float As[16][129];   // [k][row], padded
    __shared__ float Bs[16][128];   // [k][col]

    const int tid = threadIdx.x;
    const int tx = tid & 15;        // 0..15
    const int ty = tid >> 4;        // 0..15
    const int m0 = blockIdx.y * 128;
    const int n0 = blockIdx.x * 128;

    float acc[8][8];
#pragma unroll
    for (int i = 0; i < 8; i++)
#pragma unroll
        for (int j = 0; j < 8; j++) acc[i][j] = 0.0f;

    for (int k0 = 0; k0 < K; k0 += 16) {
        // Load A tile: 128 rows x 16 k  (512 float4 / 256 threads = 2 each)
#pragma unroll
        for (int r = 0; r < 2; r++) {
            int e = tid + 256 * r;          // 0..511
            int row = e >> 2;               // 4 float4 per row
            int kq = (e & 3) * 4;
            float4 v = *(const float4*)(A + (size_t)(m0 + row) * K + k0 + kq);
            As[kq + 0][row] = v.x;
            As[kq + 1][row] = v.y;
            As[kq + 2][row] = v.z;
            As[kq + 3][row] = v.w;
        }
        // Load B tile: 16 k x 128 cols (512 float4 / 256 threads = 2 each)
#pragma unroll
        for (int r = 0; r < 2; r++) {
            int e = tid + 256 * r;
            int kr = e >> 5;                // 32 float4 per k-row
            int nq = (e & 31) * 4;
            *(float4*)&Bs[kr][nq] =
                *(const float4*)(Bm + (size_t)(k0 + kr) * N + n0 + nq);
        }
        __syncthreads();

#pragma unroll
        for (int k = 0; k < 16; k++) {
            float a[8], b[8];
#pragma unroll
            for (int i = 0; i < 8; i++) a[i] = As[k][ty + 16 * i];
#pragma unroll
            for (int j = 0; j < 8; j++) b[j] = Bs[k][tx + 16 * j];
#pragma unroll
            for (int i = 0; i < 8; i++)
#pragma unroll
                for (int j = 0; j < 8; j++) acc[i][j] += a[i] * b[j];
        }
        __syncthreads();
    }

#pragma unroll
    for (int i = 0; i < 8; i++) {
        const int m = m0 + ty + 16 * i;
#pragma unroll
        for (int j = 0; j < 8; j++) {
            const int n = n0 + tx + 16 * j;
            C[(size_t)m * N + n] = acc[i][j] + bias[n];
        }
    }
}

__global__ void __launch_bounds__(256)
qkv_gemm_kernel(const float* __restrict__ x, const float* __restrict__ W,
                const float* __restrict__ b)
{
    gemm_body(x, W, b, g_qkv, B_ * N_, QKV3, C_);
}

__global__ void __launch_bounds__(256)
proj_gemm_kernel(const float* __restrict__ W, const float* __restrict__ b,
                 float* __restrict__ out)
{
    gemm_body(g_att, W, b, out, B_ * N_, C_, C_);
}

// ---------------------------------------------------------------------------
// Flash-style attention, fp32.
// Grid: (N/128, H, B). Block: 256 threads (16x16), 128 query rows per CTA.
// Online softmax over 128-key tiles; P staged in SMEM for the PV contraction.
// ---------------------------------------------------------------------------
#define QS_STRIDE 65
#define PS_STRIDE 132
#define ATT_SMEM_FLOATS (128 * QS_STRIDE * 3 + 128 * PS_STRIDE)

__global__ void __launch_bounds__(256)
attention_kernel()
{
    const int qt = blockIdx.x;   // query tile
    const int h  = blockIdx.y;
    const int b  = blockIdx.z;

    extern __shared__ float sm[];
    float* Qs = sm;                              // [128][65]
    float* Ks = Qs + 128 * QS_STRIDE;            // [128][65]
    float* Vs = Ks + 128 * QS_STRIDE;            // [128][65]
    float* Ps = Vs + 128 * QS_STRIDE;            // [128][132]

    const int tid = threadIdx.x;
    const int tx = tid & 15;
    const int ty = tid >> 4;

    const size_t base = (size_t)b * N_ * QKV3;
    const int qoff = h * D_;               // t = 0
    const int koff = C_ + h * D_;          // t = 1
    const int voff = 2 * C_ + h * D_;      // t = 2

    // Load Q tile: 128 rows x 64 d  (2048 float4 / 256 threads = 8 each)
#pragma unroll
    for (int r = 0; r < 8; r++) {
        int e = tid + 256 * r;
        int row = e >> 4;
        int d4 = (e & 15) * 4;
        float4 v = *(const float4*)(g_qkv + base +
                                    (size_t)(qt * 128 + row) * QKV3 + qoff + d4);
        Qs[row * QS_STRIDE + d4 + 0] = v.x;
        Qs[row * QS_STRIDE + d4 + 1] = v.y;
        Qs[row * QS_STRIDE + d4 + 2] = v.z;
        Qs[row * QS_STRIDE + d4 + 3] = v.w;
    }

    float m_i[8], l_i[8], o[8][4];
#pragma unroll
    for (int i = 0; i < 8; i++) {
        m_i[i] = -1e30f;
        l_i[i] = 0.0f;
#pragma unroll
        for (int c = 0; c < 4; c++) o[i][c] = 0.0f;
    }

    const float scale = 0.125f;   // D^-0.5 = 64^-0.5

    for (int kt = 0; kt < N_ / 128; kt++) {
        __syncthreads();   // prior-iter Ps/Vs/Ks consumers done (also covers Q load)

        // Load K and V tiles (128 x 64 each)
#pragma unroll
        for (int r = 0; r < 8; r++) {
            int e = tid + 256 * r;
            int row = e >> 4;
            int d4 = (e & 15) * 4;
            const size_t g = base + (size_t)(kt * 128 + row) * QKV3;
            float4 kv4 = *(const float4*)(g_qkv + g + koff + d4);
            Ks[row * QS_STRIDE + d4 + 0] = kv4.x;
            Ks[row * QS_STRIDE + d4 + 1] = kv4.y;
            Ks[row * QS_STRIDE + d4 + 2] = kv4.z;
            Ks[row * QS_STRIDE + d4 + 3] = kv4.w;
            float4 vv4 = *(const float4*)(g_qkv + g + voff + d4);
            Vs[row * QS_STRIDE + d4 + 0] = vv4.x;
            Vs[row * QS_STRIDE + d4 + 1] = vv4.y;
            Vs[row * QS_STRIDE + d4 + 2] = vv4.z;
            Vs[row * QS_STRIDE + d4 + 3] = vv4.w;
        }
        __syncthreads();

        // S = Q @ K^T  (128x128, 8x8 per thread, strided ownership)
        float s[8][8];
#pragma unroll
        for (int i = 0; i < 8; i++)
#pragma unroll
            for (int j = 0; j < 8; j++) s[i][j] = 0.0f;

#pragma unroll
        for (int d = 0; d < D_; d++) {
            float a[8], kb[8];
#pragma unroll
            for (int i = 0; i < 8; i++) a[i] = Qs[(ty + 16 * i) * QS_STRIDE + d];
#pragma unroll
            for (int j = 0; j < 8; j++) kb[j] = Ks[(tx + 16 * j) * QS_STRIDE + d];
#pragma unroll
            for (int i = 0; i < 8; i++)
#pragma unroll
                for (int j = 0; j < 8; j++) s[i][j] += a[i] * kb[j];
        }

        // Online softmax (row reductions across the 16 tx lanes of each ty group)
#pragma unroll
        for (int i = 0; i < 8; i++) {
            float mx = -1e30f;
#pragma unroll
            for (int j = 0; j < 8; j++) {
                s[i][j] *= scale;
                mx = fmaxf(mx, s[i][j]);
            }
#pragma unroll
            for (int off = 8; off > 0; off >>= 1)
                mx = fmaxf(mx, __shfl_xor_sync(0xffffffffu, mx, off));

            const float m_new = fmaxf(m_i[i], mx);
            const float alpha = __expf(m_i[i] - m_new);
            float lsum = 0.0f;
#pragma unroll
            for (int j = 0; j < 8; j++) {
                float p = __expf(s[i][j] - m_new);
                s[i][j] = p;
                lsum += p;
            }
#pragma unroll
            for (int off = 8; off > 0; off >>= 1)
                lsum += __shfl_xor_sync(0xffffffffu, lsum, off);

            l_i[i] = l_i[i] * alpha + lsum;
            m_i[i] = m_new;
#pragma unroll
            for (int c = 0; c < 4; c++) o[i][c] *= alpha;

#pragma unroll
            for (int j = 0; j < 8; j++)
                Ps[(ty + 16 * i) * PS_STRIDE + tx + 16 * j] = s[i][j];
        }
        __syncthreads();

        // O += P @ V   (O ownership: rows ty+16i, cols tx+16c)
#pragma unroll 4
        for (int kk = 0; kk < 128; kk++) {
            float vv[4];
#pragma unroll
            for (int c = 0; c < 4; c++) vv[c] = Vs[kk * QS_STRIDE + tx + 16 * c];
#pragma unroll
            for (int i = 0; i < 8; i++) {
                const float p = Ps[(ty + 16 * i) * PS_STRIDE + kk];
#pragma unroll
                for (int c = 0; c < 4; c++) o[i][c] += p * vv[c];
            }
        }
    }

    // Normalize and write attention output [B*N, C]
#pragma unroll
    for (int i = 0; i < 8; i++) {
        const float inv = 1.0f / l_i[i];
        const int n = qt * 128 + ty + 16 * i;
#pragma unroll
        for (int c = 0; c < 4; c++) {
            g_att[((size_t)b * N_ + n) * C_ + h * D_ + tx + 16 * c] = o[i][c] * inv;
        }
    }
}

// ---------------------------------------------------------------------------
// Launch
// ---------------------------------------------------------------------------
extern "C" void kernel_launch(void* const* d_in, const int* in_sizes, int n_in,
                              void* d_out, int out_size)
{
    const float* x     = (const float*)d_in[0];
    const float* Wqkv  = (const float*)d_in[1];
    const float* bqkv  = (const float*)d_in[2];
    const float* Wproj = (const float*)d_in[3];
    const float* bproj = (const float*)d_in[4];
    float* out = (float*)d_out;

    const dim3 blk(256);

    // 1) qkv = x @ Wqkv + bqkv        [8192, 2304]
    qkv_gemm_kernel<<<dim3(QKV3 / 128, (B_ * N_) / 128), blk>>>(x, Wqkv, bqkv);

    // 2) flash attention -> g_att     [8192, 768]
    const size_t att_smem = (size_t)ATT_SMEM_FLOATS * sizeof(float);  // ~163.5 KB
    cudaFuncSetAttribute(attention_kernel,
                         cudaFuncAttributeMaxDynamicSharedMemorySize,
                         (int)att_smem);
    attention_kernel<<<dim3(N_ / 128, H_, B_), blk, att_smem>>>();

    // 3) out = g_att @ Wproj + bproj  [8192, 768]
    proj_gemm_kernel<<<dim3(C_ / 128, (B_ * N_) / 128), blk>>>(Wproj, bproj, out);
}

// round 2
// speedup vs baseline: 1.0025x; 1.0025x over previous
#include <cuda_runtime.h>

#define B_ 8
#define N_ 1024
#define C_ 768
#define H_ 12
#define D_ 64
#define QKV3 (3 * C_)

// Scratch (static device arrays — allocation-free per harness rules)
__device__ float g_qkv[(size_t)B_ * N_ * QKV3];   // 75.5 MB: [B*N, 3C] = [.., t*768 + h*64 + d]
__device__ float g_att[(size_t)B_ * N_ * C_];     // 25.2 MB: attention output [B*N, C]

// ---------------------------------------------------------------------------
// Generic fp32 GEMM body: C[M,N] = A[M,K] @ B[K,N] + bias[N]
// 128x128x16 tile, 256 threads, 8x8 per-thread microtile (strided ownership).
// Assumes M%128==0, N%128==0, K%16==0 (true for all three call sites).
// ---------------------------------------------------------------------------
__device__ __forceinline__ void gemm_body(
    const float* __restrict__ A, const float* __restrict__ Bm,
    const float* __restrict__ bias, float* __restrict__ C,
    int M, int N, int K)
{
    __shared__ float As[16][129];   // [k][row], padded
    __shared__ float Bs[16][128];   // [k][col]

    const int tid = threadIdx.x;
    const int tx = tid & 15;        // 0..15
    const int ty = tid >> 4;        // 0..15
    const int m0 = blockIdx.y * 128;
    const int n0 = blockIdx.x * 128;

    float acc[8][8];
#pragma unroll
    for (int i = 0; i < 8; i++)
#pragma unroll
        for (int j = 0; j < 8; j++) acc[i][j] = 0.0f;

    for (int k0 = 0; k0 < K; k0 += 16) {
        // Load A tile: 128 rows x 16 k  (512 float4 / 256 threads = 2 each)
#pragma unroll
        for (int r = 0; r < 2; r++) {
            int e = tid + 256 * r;          // 0..511
            int row = e >> 2;               // 4 float4 per row
            int kq = (e & 3) * 4;
            float4 v = *(const float4*)(A + (size_t)(m0 + row) * K + k0 + kq);
            As[kq + 0][row] = v.x;
            As[kq + 1][row] = v.y;
            As[kq + 2][row] = v.z;
            As[kq + 3][row] = v.w;
        }
        // Load B tile: 16 k x 128 cols (512 float4 / 256 threads = 2 each)
#pragma unroll
        for (int r = 0; r < 2; r++) {
            int e = tid + 256 * r;
            int kr = e >> 5;                // 32 float4 per k-row
            int nq = (e & 31) * 4;
            *(float4*)&Bs[kr][nq] =
                *(const float4*)(Bm + (size_t)(k0 + kr) * N + n0 + nq);
        }
        __syncthreads();

#pragma unroll
        for (int k = 0; k < 16; k++) {
            float a[8], b[8];
#pragma unroll
            for (int i = 0; i < 8; i++) a[i] = As[k][ty + 16 * i];
#pragma unroll
            for (int j = 0; j < 8; j++) b[j] = Bs[k][tx + 16 * j];
#pragma unroll
            for (int i = 0; i < 8; i++)
#pragma unroll
                for (int j = 0; j < 8; j++) acc[i][j] += a[i] * b[j];
        }
        __syncthreads();
    }

#pragma unroll
    for (int i = 0; i < 8; i++) {
        const int m = m0 + ty + 16 * i;
#pragma unroll
        for (int j = 0; j < 8; j++) {
            const int n = n0 + tx + 16 * j;
            C[(size_t)m * N + n] = acc[i][j] + bias[n];
        }
    }
}

__global__ void __launch_bounds__(256)
qkv_gemm_kernel(const float* __restrict__ x, const float* __restrict__ W,
                const float* __restrict__ b)
{
    gemm_body(x, W, b, g_qkv, B_ * N_, QKV3, C_);
}

__global__ void __launch_bounds__(256)
proj_gemm_kernel(const float* __restrict__ W, const float* __restrict__ b,
                 float* __restrict__ out)
{
    gemm_body(g_att, W, b, out, B_ * N_, C_, C_);
}

// ---------------------------------------------------------------------------
// Flash-style attention, fp32.
// Grid: (N/128, H, B). Block: 256 threads (16x16), 128 query rows per CTA.
// Online softmax over 128-key tiles; P staged in SMEM for the PV contraction.
// ---------------------------------------------------------------------------
#define QS_STRIDE 65
#define PS_STRIDE 132
#define ATT_SMEM_FLOATS (128 * QS_STRIDE * 3 + 128 * PS_STRIDE)

__global__ void __launch_bounds__(256)
attention_kernel()
{
    const int qt = blockIdx.x;   // query tile
    const int h  = blockIdx.y;
    const int b  = blockIdx.z;

    extern __shared__ float sm[];
    float* Qs = sm;                              // [128][65]
    float* Ks = Qs + 128 * QS_STRIDE;            // [128][65]
    float* Vs = Ks + 128 * QS_STRIDE;            // [128][65]
    float* Ps = Vs + 128 * QS_STRIDE;            // [128][132]

    const int tid = threadIdx.x;
    const int tx = tid & 15;
    const int ty = tid >> 4;

    const size_t base = (size_t)b * N_ * QKV3;
    const int qoff = h * D_;               // t = 0
    const int koff = C_ + h * D_;          // t = 1
    const int voff = 2 * C_ + h * D_;      // t = 2

    // Load Q tile: 128 rows x 64 d  (2048 float4 / 256 threads = 8 each)
#pragma unroll
    for (int r = 0; r < 8; r++) {
        int e = tid + 256 * r;
        int row = e >> 4;
        int d4 = (e & 15) * 4;
        float4 v = *(const float4*)(g_qkv + base +
                                    (size_t)(qt * 128 + row) * QKV3 + qoff + d4);
        Qs[row * QS_STRIDE + d4 + 0] = v.x;
        Qs[row * QS_STRIDE + d4 + 1] = v.y;
        Qs[row * QS_STRIDE + d4 + 2] = v.z;
        Qs[row * QS_STRIDE + d4 + 3] = v.w;
    }

    float m_i[8], l_i[8], o[8][4];
#pragma unroll
    for (int i = 0; i < 8; i++) {
        m_i[i] = -1e30f;
        l_i[i] = 0.0f;
#pragma unroll
        for (int c = 0; c < 4; c++) o[i][c] = 0.0f;
    }

    const float scale = 0.125f;   // D^-0.5 = 64^-0.5

    for (int kt = 0; kt < N_ / 128; kt++) {
        __syncthreads();   // prior-iter Ps/Vs/Ks consumers done (also covers Q load)

        // Load K and V tiles (128 x 64 each)
#pragma unroll
        for (int r = 0; r < 8; r++) {
            int e = tid + 256 * r;
            int row = e >> 4;
            int d4 = (e & 15) * 4;
            const size_t g = base + (size_t)(kt * 128 + row) * QKV3;
            float4 kv4 = *(const float4*)(g_qkv + g + koff + d4);
            Ks[row * QS_STRIDE + d4 + 0] = kv4.x;
            Ks[row * QS_STRIDE + d4 + 1] = kv4.y;
            Ks[row * QS_STRIDE + d4 + 2] = kv4.z;
            Ks[row * QS_STRIDE + d4 + 3] = kv4.w;
            float4 vv4 = *(const float4*)(g_qkv + g + voff + d4);
            Vs[row * QS_STRIDE + d4 + 0] = vv4.x;
            Vs[row * QS_STRIDE + d4 + 1] = vv4.y;
            Vs[row * QS_STRIDE + d4 + 2] = vv4.z;
            Vs[row * QS_STRIDE + d4 + 3] = vv4.w;
        }
        __syncthreads();

        // S = Q @ K^T  (128x128, 8x8 per thread, strided ownership)
        float s[8][8];
#pragma unroll
        for (int i = 0; i < 8; i++)
#pragma unroll
            for (int j = 0; j < 8; j++) s[i][j] = 0.0f;

#pragma unroll
        for (int d = 0; d < D_; d++) {
            float a[8], kb[8];
#pragma unroll
            for (int i = 0; i < 8; i++) a[i] = Qs[(ty + 16 * i) * QS_STRIDE + d];
#pragma unroll
            for (int j = 0; j < 8; j++) kb[j] = Ks[(tx + 16 * j) * QS_STRIDE + d];
#pragma unroll
            for (int i = 0; i < 8; i++)
#pragma unroll
                for (int j = 0; j < 8; j++) s[i][j] += a[i] * kb[j];
        }

        // Online softmax (row reductions across the 16 tx lanes of each ty group)
#pragma unroll
        for (int i = 0; i < 8; i++) {
            float mx = -1e30f;
#pragma unroll
            for (int j = 0; j < 8; j++) {
                s[i][j] *= scale;
                mx = fmaxf(mx, s[i][j]);
            }
#pragma unroll
            for (int off = 8; off > 0; off >>= 1)
                mx = fmaxf(mx, __shfl_xor_sync(0xffffffffu, mx, off));

            const float m_new = fmaxf(m_i[i], mx);
            const float alpha = __expf(m_i[i] - m_new);
            float lsum = 0.0f;
#pragma unroll
            for (int j = 0; j < 8; j++) {
                float p = __expf(s[i][j] - m_new);
                s[i][j] = p;
                lsum += p;
            }
#pragma unroll
            for (int off = 8; off > 0; off >>= 1)
                lsum += __shfl_xor_sync(0xffffffffu, lsum, off);

            l_i[i] = l_i[i] * alpha + lsum;
            m_i[i] = m_new;
#pragma unroll
            for (int c = 0; c < 4; c++) o[i][c] *= alpha;

#pragma unroll
            for (int j = 0; j < 8; j++)
                Ps[(ty + 16 * i) * PS_STRIDE + tx + 16 * j] = s[i][j];
        }
        __syncthreads();

        // O += P @ V   (O ownership: rows ty+16i, cols tx+16c)
#pragma unroll 4
        for (int kk = 0; kk < 128; kk++) {
            float vv[4];
#pragma unroll
            for (int c = 0; c < 4; c++) vv[c] = Vs[kk * QS_STRIDE + tx + 16 * c];
#pragma unroll
            for (int i = 0; i < 8; i++) {
                const float p = Ps[(ty + 16 * i) * PS_STRIDE + kk];
#pragma unroll
                for (int c = 0; c < 4; c++) o[i][c] += p * vv[c];
            }
        }
    }

    // Normalize and write attention output [B*N, C]
#pragma unroll
    for (int i = 0; i < 8; i++) {
        const float inv = 1.0f / l_i[i];
        const int n = qt * 128 + ty + 16 * i;
#pragma unroll
        for (int c = 0; c < 4; c++) {
            g_att[((size_t)b * N_ + n) * C_ + h * D_ + tx + 16 * c] = o[i][c] * inv;
        }
    }
}

// ---------------------------------------------------------------------------
// Launch
// ---------------------------------------------------------------------------
extern "C" void kernel_launch(void* const* d_in, const int* in_sizes, int n_in,
                              void* d_out, int out_size)
{
    const float* x     = (const float*)d_in[0];
    const float* Wqkv  = (const float*)d_in[1];
    const float* bqkv  = (const float*)d_in[2];
    const float* Wproj = (const float*)d_in[3];
    const float* bproj = (const float*)d_in[4];
    float* out = (float*)d_out;

    const dim3 blk(256);

    // 1) qkv = x @ Wqkv + bqkv        [8192, 2304]
    qkv_gemm_kernel<<<dim3(QKV3 / 128, (B_ * N_) / 128), blk>>>(x, Wqkv, bqkv);

    // 2) flash attention -> g_att     [8192, 768]
    const size_t att_smem = (size_t)ATT_SMEM_FLOATS * sizeof(float);  // ~163.5 KB
    cudaFuncSetAttribute(attention_kernel,
                         cudaFuncAttributeMaxDynamicSharedMemorySize,
                         (int)att_smem);
    attention_kernel<<<dim3(N_ / 128, H_, B_), blk, att_smem>>>();

    // 3) out = g_att @ Wproj + bproj  [8192, 768]
    proj_gemm_kernel<<<dim3(C_ / 128, (B_ * N_) / 128), blk>>>(Wproj, bproj, out);
}